// round 14
// baseline (speedup 1.0000x reference)
#include <cuda_runtime.h>
#include <math.h>

#define BATCH 16
#define TQ 4
#define DMODEL 2048
#define NH 8
#define NG 4
#define GSZ 2
#define HD 256
#define KVBLK 16
#define WINDOW 1024
#define NBLK 257
#define NTOK 64          // BATCH*TQ
#define NFQKV 4096       // 2048 q + 1024 k + 1024 v
#define NSPLIT 8         // attention KV splits
#define NPART NSPLIT     // partials per query (kh merged in-kernel)
#define NKSPL 8          // GEMM split-K

typedef unsigned long long u64;

// ---------------- scratch (device globals; no allocation allowed) ----------
__device__ float g_part_qkv[NKSPL][NTOK][NFQKV];        // 8 MB
__device__ float g_obuf[NTOK][DMODEL];                  // attention output (row-major)
__device__ float g_q[NTOK][NH][HD];
__device__ float g_k[NTOK][NG][HD];
__device__ float g_v[NTOK][NG][HD];
__device__ float g_cos[NTOK][HD / 2];
__device__ float g_sin[NTOK][HD / 2];
__device__ float g_pacc[BATCH * NG * 8 * NPART][HD];    // 4 MB
__device__ float g_pm[BATCH * NG * 8 * NPART];
__device__ float g_pl[BATCH * NG * 8 * NPART];
__device__ float g_part_out[NKSPL][NTOK][DMODEL];       // 4 MB

// ---------------- cp.async / mma / f32x2 helpers ----------------------------
__device__ __forceinline__ void cp_async16(void* dst, const void* src)
{
    unsigned d = (unsigned)__cvta_generic_to_shared(dst);
    asm volatile("cp.async.cg.shared.global [%0], [%1], 16;\n" :: "r"(d), "l"(src));
}
__device__ __forceinline__ void cp_commit()
{
    asm volatile("cp.async.commit_group;\n");
}
template <int N>
__device__ __forceinline__ void cp_wait()
{
    asm volatile("cp.async.wait_group %0;\n" :: "n"(N));
}
__device__ __forceinline__ unsigned f2tf32(float f)
{
    unsigned u;
    asm("cvt.rna.tf32.f32 %0, %1;" : "=r"(u) : "f"(f));
    return u;
}
__device__ __forceinline__ void mma_tf32(float* d, const unsigned* a, const unsigned* b)
{
    asm volatile(
        "mma.sync.aligned.m16n8k8.row.col.f32.tf32.tf32.f32 "
        "{%0,%1,%2,%3}, {%4,%5,%6,%7}, {%8,%9}, {%0,%1,%2,%3};\n"
        : "+f"(d[0]), "+f"(d[1]), "+f"(d[2]), "+f"(d[3])
        : "r"(a[0]), "r"(a[1]), "r"(a[2]), "r"(a[3]), "r"(b[0]), "r"(b[1]));
}
__device__ __forceinline__ void fma2(u64& acc, u64 a, u64 b)
{
    asm("fma.rn.f32x2 %0, %1, %2, %0;" : "+l"(acc) : "l"(a), "l"(b));
}
__device__ __forceinline__ u64 mul2(u64 a, u64 b)
{
    u64 r;
    asm("mul.rn.f32x2 %0, %1, %2;" : "=l"(r) : "l"(a), "l"(b));
    return r;
}
__device__ __forceinline__ u64 pack2(float lo, float hi)
{
    u64 r;
    asm("mov.b64 %0, {%1, %2};" : "=l"(r) : "f"(lo), "f"(hi));
    return r;
}
__device__ __forceinline__ float sum2(u64 v)
{
    float lo, hi;
    asm("mov.b64 {%0, %1}, %2;" : "=f"(lo), "=f"(hi) : "l"(v));
    return lo + hi;
}

// ---------------- RoPE table (fp64 accuracy) --------------------------------
__global__ void k_rope_table(const int* __restrict__ kv_lens)
{
    int idx = blockIdx.x * blockDim.x + threadIdx.x;   // 64*128
    if (idx >= NTOK * 128) return;
    int bt = idx >> 7, j = idx & 127;
    int b = bt >> 2, t = bt & 3;
    int pos = kv_lens[b] + t;
    double inv = exp(-((double)j / 128.0) * log(10000.0));
    double ang = (double)pos * inv;
    double sd, cd;
    sincos(ang, &sd, &cd);
    g_cos[bt][j] = (float)cd;
    g_sin[bt][j] = (float)sd;
}

// ---------------- tf32 tensor-core split-K GEMM (R10 config) ----------------
// C[64, NF] = A[64, 2048] * W[NF, 2048]^T, A row-major (stride 2048).
// CTA: 64 tokens x 64 features, Kc = 256 (8 chunks of 32, double-buffered).
template <int NF>
__device__ __forceinline__ void gemm_tc(
    const float* __restrict__ A,
    const float* __restrict__ W0, int n0,
    const float* __restrict__ W1, int n1,
    const float* __restrict__ W2,
    float* __restrict__ part)
{
    __shared__ float As[2][64][36];   // [m][k], stride 36 -> conflict-free frags
    __shared__ float Ws[2][64][36];   // [n][k]

    const int fbase = blockIdx.x * 64;
    const int split = blockIdx.y;
    const int tid = threadIdx.x;
    const int lane = tid & 31, warp = tid >> 5;
    const int wm = warp >> 2, wn = warp & 3;
    const int kbase = split * 256;
    const int gid = lane >> 2, tig = lane & 3;

    float acc[2][2][4] = {};

    auto issue = [&](int c, int buf) {
        const int kg = kbase + c * 32;
#pragma unroll
        for (int r = 0; r < 2; r++) {
            int o = tid * 2 + r;                 // 0..511
            int row = o >> 3, seg = o & 7;       // 64 rows x 8 chunks
            cp_async16(&As[buf][row][seg * 4],
                       &A[(size_t)row * DMODEL + kg + seg * 4]);
        }
#pragma unroll
        for (int r = 0; r < 2; r++) {
            int o = tid * 2 + r;
            int n = o >> 3, seg = o & 7;
            int f = fbase + n;
            const float* wr;
            if (f < n0)            wr = W0 + (size_t)f * DMODEL;
            else if (f < n0 + n1)  wr = W1 + (size_t)(f - n0) * DMODEL;
            else                   wr = W2 + (size_t)(f - n0 - n1) * DMODEL;
            cp_async16(&Ws[buf][n][seg * 4], wr + kg + seg * 4);
        }
        cp_commit();
    };

    issue(0, 0);
    int buf = 0;
    for (int c = 0; c < 8; c++) {
        if (c < 7) { issue(c + 1, buf ^ 1); cp_wait<1>(); }
        else       cp_wait<0>();
        __syncthreads();
#pragma unroll
        for (int ks = 0; ks < 4; ks++) {
            const int k = ks * 8 + tig;
            unsigned aF[2][4], bF[2][2];
#pragma unroll
            for (int mt = 0; mt < 2; mt++) {
                int m = wm * 32 + mt * 16 + gid;
                aF[mt][0] = f2tf32(As[buf][m][k]);
                aF[mt][1] = f2tf32(As[buf][m + 8][k]);
                aF[mt][2] = f2tf32(As[buf][m][k + 4]);
                aF[mt][3] = f2tf32(As[buf][m + 8][k + 4]);
            }
#pragma unroll
            for (int nt = 0; nt < 2; nt++) {
                int n = wn * 16 + nt * 8 + gid;
                bF[nt][0] = f2tf32(Ws[buf][n][k]);
                bF[nt][1] = f2tf32(Ws[buf][n][k + 4]);
            }
#pragma unroll
            for (int mt = 0; mt < 2; mt++)
#pragma unroll
                for (int nt = 0; nt < 2; nt++)
                    mma_tf32(acc[mt][nt], aF[mt], bF[nt]);
        }
        buf ^= 1;
        __syncthreads();
    }

#pragma unroll
    for (int mt = 0; mt < 2; mt++)
#pragma unroll
        for (int nt = 0; nt < 2; nt++) {
            int m = wm * 32 + mt * 16 + gid;
            int f = fbase + wn * 16 + nt * 8 + tig * 2;
            *(float2*)&part[((size_t)split * NTOK + m) * NF + f] =
                make_float2(acc[mt][nt][0], acc[mt][nt][1]);
            *(float2*)&part[((size_t)split * NTOK + m + 8) * NF + f] =
                make_float2(acc[mt][nt][2], acc[mt][nt][3]);
        }
}

__global__ void __launch_bounds__(256)
k_gemm_qkv(const float* __restrict__ x,
           const float* __restrict__ Wq,
           const float* __restrict__ Wk,
           const float* __restrict__ Wv)
{
    gemm_tc<NFQKV>(x, Wq, 2048, Wk, 1024, Wv, &g_part_qkv[0][0][0]);
}

__global__ void __launch_bounds__(256)
k_gemm_o(const float* __restrict__ Wo)
{
    gemm_tc<DMODEL>(&g_obuf[0][0], Wo, 2048, Wo, 0, Wo, &g_part_out[0][0][0]);
}

// ---------------- split-K reduce + RMSNorm + RoPE (float4, 64 threads) ------
__global__ void k_normrope(const float* __restrict__ q_scale,
                           const float* __restrict__ k_scale)
{
    const int bt = blockIdx.x;
    const int u = blockIdx.y;
    const int t4 = threadIdx.x;        // 0..63
    const int d = t4 * 4;

    int f;
    if (u < 8)       f = u * HD + d;
    else if (u < 12) f = 2048 + (u - 8) * HD + d;
    else             f = 3072 + (u - 12) * HD + d;

    float4 v = {0.f, 0.f, 0.f, 0.f};
#pragma unroll
    for (int s = 0; s < NKSPL; s++) {
        float4 p = *(const float4*)&g_part_qkv[s][bt][f];
        v.x += p.x; v.y += p.y; v.z += p.z; v.w += p.w;
    }

    if (u >= 12) { *(float4*)&g_v[bt][u - 12][d] = v; return; }

    __shared__ __align__(16) float wsum[4];
    __shared__ __align__(16) float sx[256];

    float ss = v.x * v.x + v.y * v.y + v.z * v.z + v.w * v.w;
#pragma unroll
    for (int o = 16; o; o >>= 1) ss += __shfl_xor_sync(0xffffffffu, ss, o);
    if ((t4 & 31) == 0) wsum[t4 >> 5] = ss;
    __syncthreads();
    float rn = rsqrtf((wsum[0] + wsum[1]) / (float)HD + 1e-6f);

    float4 sc = (u < 8) ? *(const float4*)&q_scale[d]
                        : *(const float4*)&k_scale[d];
    float4 sv;
    sv.x = v.x * rn * (1.f + sc.x);
    sv.y = v.y * rn * (1.f + sc.y);
    sv.z = v.z * rn * (1.f + sc.z);
    sv.w = v.w * rn * (1.f + sc.w);
    *(float4*)&sx[d] = sv;
    __syncthreads();

    const int j = d & 127;
    float4 c = *(const float4*)&g_cos[bt][j];
    float4 s = *(const float4*)&g_sin[bt][j];
    float4 x1 = *(const float4*)&sx[j];
    float4 x2 = *(const float4*)&sx[j + 128];
    float4 o;
    if (d < 128) {
        o.x = x1.x * c.x - x2.x * s.x; o.y = x1.y * c.y - x2.y * s.y;
        o.z = x1.z * c.z - x2.z * s.z; o.w = x1.w * c.w - x2.w * s.w;
    } else {
        o.x = x2.x * c.x + x1.x * s.x; o.y = x2.y * c.y + x1.y * s.y;
        o.z = x2.z * c.z + x1.z * s.z; o.w = x2.w * c.w + x1.w * s.w;
    }
    if (u < 8) *(float4*)&g_q[bt][u][d] = o;
    else       *(float4*)&g_k[bt][u - 8][d] = o;
}

// ---------------- attention tile loader: one pointer calc, K+V groups -------
__device__ __forceinline__ void attn_issue_kv(
    float* __restrict__ sK, float* __restrict__ sV,
    int k0, int kvl, int hi, int b, int g,
    const float* __restrict__ kb, const float* __restrict__ vb,
    const int* __restrict__ btab, int tid)
{
    const int key = tid >> 4;
    const int j = tid & 15;
    const int kpos = k0 + key;
    const float* kp;
    const float* vp;
    if (kpos < kvl) {
        int blk = btab[b * NBLK + (kpos >> 4)];
        size_t off = (((size_t)blk * NG + g) * KVBLK + (kpos & 15)) * HD;
        kp = kb + off; vp = vb + off;
    } else if (kpos <= hi) {
        int tf = kpos - kvl;
        kp = &g_k[b * TQ + tf][g][0];
        vp = &g_v[b * TQ + tf][g][0];
    } else {
        kp = &g_k[0][0][0];
        vp = &g_v[0][0][0];
    }
    float* dk = sK + key * HD;
    float* dv = sV + key * HD;
#pragma unroll
    for (int c = 0; c < 4; c++) {
        int f = (j + 16 * c) * 4;
        cp_async16(dk + f, kp + f);
    }
    cp_commit();                      // K group
#pragma unroll
    for (int c = 0; c < 4; c++) {
        int f = (j + 16 * c) * 4;
        cp_async16(dv + f, vp + f);
    }
    cp_commit();                      // V group
}

// ---------------- flash-decode attention: 2q x 8k, in-kernel kh merge -------
__global__ void __launch_bounds__(256, 3)
k_attn(const float* __restrict__ k_blocks,
       const float* __restrict__ v_blocks,
       const int* __restrict__ block_tables,
       const int* __restrict__ kv_lens)
{
    extern __shared__ float sm[];
    float* sK0 = sm;
    float* sV0 = sm + 2 * 16 * HD;

    const int bg = blockIdx.x;
    const int b = bg >> 2, g = bg & 3;
    const int sp = blockIdx.y;
    const int tid = threadIdx.x;
    const int warp = tid >> 5, lane = tid & 31;
    const int qp = warp >> 1;
    const int kh = warp & 1;

    const int kvl = kv_lens[b];
    const int lo = max(0, kvl - (WINDOW - 1));
    const int hi = kvl + 3;
    const int L = hi - lo + 1;
    const int chunk = (L + NSPLIT - 1) / NSPLIT;
    const int kstart = lo + sp * chunk;
    const int kend = min(kstart + chunk, hi + 1);

    // queries packed as 4 x f32x2 per half (8 dims per lane)
    u64 qv[2][4];
    int post[2];
#pragma unroll
    for (int j = 0; j < 2; j++) {
        int qi = qp * 2 + j;
        int gi = qi >> 2, t = qi & 3;
        ulonglong2 a = *(const ulonglong2*)&g_q[b * TQ + t][g * GSZ + gi][lane * 4];
        ulonglong2 c = *(const ulonglong2*)&g_q[b * TQ + t][g * GSZ + gi][128 + lane * 4];
        qv[j][0] = a.x; qv[j][1] = a.y; qv[j][2] = c.x; qv[j][3] = c.y;
        post[j] = kvl + t;
    }

    float m[2] = {-INFINITY, -INFINITY};
    float l[2] = {0.f, 0.f};
    u64 av[2][4] = {};          // packed accumulators (8 dims per lane)

    if (kstart < kend)
        attn_issue_kv(sK0, sV0, kstart, kvl, hi, b, g,
                      k_blocks, v_blocks, block_tables, tid);

    int buf = 0;
    for (int k0 = kstart; k0 < kend; k0 += 16) {
        const int nk = min(16, kend - k0);
        const bool more = (k0 + 16 < kend);
        if (more) {
            attn_issue_kv(sK0 + (buf ^ 1) * 16 * HD, sV0 + (buf ^ 1) * 16 * HD,
                          k0 + 16, kvl, hi, b, g,
                          k_blocks, v_blocks, block_tables, tid);
            cp_wait<3>();       // K_i done; V_i, K_{i+1}, V_{i+1} in flight
        } else {
            cp_wait<1>();       // K_i done; V_i in flight
        }
        __syncthreads();

        const float* K = sK0 + buf * 16 * HD;
        const float* V = sV0 + buf * 16 * HD;

        // ---- scores: packed f32x2 dot products (V still in flight) ----
        float s[2][8];
#pragma unroll
        for (int kk = 0; kk < 8; kk++) {
            const float* kr = K + (kh * 8 + kk) * HD;
            ulonglong2 kA = *(const ulonglong2*)(kr + lane * 4);
            ulonglong2 kB = *(const ulonglong2*)(kr + 128 + lane * 4);
#pragma unroll
            for (int j = 0; j < 2; j++) {
                u64 d2 = 0;                 // bits of (0.f, 0.f)
                fma2(d2, qv[j][0], kA.x);
                fma2(d2, qv[j][1], kA.y);
                fma2(d2, qv[j][2], kB.x);
                fma2(d2, qv[j][3], kB.y);
                s[j][kk] = sum2(d2);
            }
        }
#pragma unroll
        for (int j = 0; j < 2; j++)
#pragma unroll
            for (int kk = 0; kk < 8; kk++) {
                float d = s[j][kk];
#pragma unroll
                for (int o = 16; o; o >>= 1) d += __shfl_xor_sync(0xffffffffu, d, o);
                int kpos = k0 + kh * 8 + kk;
                bool ok = (kh * 8 + kk) < nk && kpos <= post[j]
                          && kpos > post[j] - WINDOW;
                s[j][kk] = ok ? d * 0.0625f : -INFINITY;
            }

        // ---- online softmax update ----
#pragma unroll
        for (int j = 0; j < 2; j++) {
            float tm = s[j][0];
#pragma unroll
            for (int kk = 1; kk < 8; kk++) tm = fmaxf(tm, s[j][kk]);
            if (tm == -INFINITY) {
#pragma unroll
                for (int kk = 0; kk < 8; kk++) s[j][kk] = 0.f;
                continue;
            }
            float mn = fmaxf(m[j], tm);
            float co = __expf(m[j] - mn);
            float ls = 0.f;
#pragma unroll
            for (int kk = 0; kk < 8; kk++) {
                s[j][kk] = __expf(s[j][kk] - mn);
                ls += s[j][kk];
            }
            l[j] = l[j] * co + ls;
            u64 cop = pack2(co, co);
#pragma unroll
            for (int i = 0; i < 4; i++) av[j][i] = mul2(av[j][i], cop);
            m[j] = mn;
        }

        if (more) cp_wait<2>();   // V_i done; next tile still in flight
        else      cp_wait<0>();
        __syncthreads();

        // ---- PV: packed f32x2 accumulate ----
#pragma unroll
        for (int kk = 0; kk < 8; kk++) {
            const float* vr = V + (kh * 8 + kk) * HD;
            ulonglong2 vA = *(const ulonglong2*)(vr + lane * 4);
            ulonglong2 vB = *(const ulonglong2*)(vr + 128 + lane * 4);
#pragma unroll
            for (int j = 0; j < 2; j++) {
                u64 pp = pack2(s[j][kk], s[j][kk]);
                fma2(av[j][0], pp, vA.x);
                fma2(av[j][1], pp, vA.y);
                fma2(av[j][2], pp, vB.x);
                fma2(av[j][3], pp, vB.y);
            }
        }
        buf ^= 1;
        __syncthreads();
    }

    // ---- merge kh=1 into kh=0 via smem (buffers free after the loop) ------
    u64* sacc = (u64*)sm;                         // 8 q x 32 lanes x 4 u64
    float* sml = sm + 2048;                       // 8 q x {m, l}
    if (kh == 1) {
#pragma unroll
        for (int j = 0; j < 2; j++) {
            int base = ((qp * 2 + j) * 32 + lane) * 4;
#pragma unroll
            for (int i = 0; i < 4; i++) sacc[base + i] = av[j][i];
            if (lane == 0) {
                sml[(qp * 2 + j) * 2 + 0] = m[j];
                sml[(qp * 2 + j) * 2 + 1] = l[j];
            }
        }
    }
    __syncthreads();
    if (kh == 0) {
#pragma unroll
        for (int j = 0; j < 2; j++) {
            int q8 = qp * 2 + j;
            float m1 = sml[q8 * 2 + 0];
            float l1 = sml[q8 * 2 + 1];
            float M = fmaxf(m[j], m1);
            float w0 = (m[j] == -INFINITY) ? 0.f : __expf(m[j] - M);
            float w1 = (m1 == -INFINITY) ? 0.f : __expf(m1 - M);
            float L = l[j] * w0 + l1 * w1;
            u64 w0p = pack2(w0, w0), w1p = pack2(w1, w1);
            int base = (q8 * 32 + lane) * 4;
#pragma unroll
            for (int i = 0; i < 4; i++) {
                u64 r = mul2(av[j][i], w0p);
                fma2(r, sacc[base + i], w1p);
                av[j][i] = r;
            }
            int pi = (bg * 8 + q8) * NSPLIT + sp;
            if (lane == 0) { g_pm[pi] = M; g_pl[pi] = L; }
            ulonglong2 oA = {av[j][0], av[j][1]};
            ulonglong2 oB = {av[j][2], av[j][3]};
            *(ulonglong2*)&g_pacc[pi][lane * 4] = oA;
            *(ulonglong2*)&g_pacc[pi][128 + lane * 4] = oB;
        }
    }
}

// ---------------- combine partial softmax (float4, 64 threads) --------------
__global__ void k_combine()
{
    const int qidx = blockIdx.x;   // 512
    const int d = threadIdx.x * 4; // 0..252

    float M = -INFINITY;
#pragma unroll
    for (int s = 0; s < NPART; s++) M = fmaxf(M, g_pm[qidx * NPART + s]);
    float Lt = 0.f;
    float4 od = {0.f, 0.f, 0.f, 0.f};
#pragma unroll
    for (int s = 0; s < NPART; s++) {
        float ms = g_pm[qidx * NPART + s];
        float w = (ms == -INFINITY) ? 0.f : __expf(ms - M);
        Lt += g_pl[qidx * NPART + s] * w;
        float4 p = *(const float4*)&g_pacc[qidx * NPART + s][d];
        od.x += p.x * w; od.y += p.y * w; od.z += p.z * w; od.w += p.w * w;
    }
    float inv = 1.f / Lt;

    int t = qidx & 3;
    int gi = (qidx >> 2) & 1;
    int g = (qidx >> 3) & 3;
    int b = qidx >> 5;
    float4 o = {od.x * inv, od.y * inv, od.z * inv, od.w * inv};
    *(float4*)&g_obuf[b * TQ + t][(g * GSZ + gi) * HD + d] = o;
}

// ---------------- final split-K reduce to output ---------------------------
__global__ void k_reduce_out(float* __restrict__ out)
{
    int idx = blockIdx.x * blockDim.x + threadIdx.x;   // 64*2048/4
    if (idx >= NTOK * DMODEL / 4) return;
    int bt = idx / (DMODEL / 4), dc = (idx % (DMODEL / 4)) * 4;
    float4 v = {0.f, 0.f, 0.f, 0.f};
#pragma unroll
    for (int s = 0; s < NKSPL; s++) {
        float4 p = *(const float4*)&g_part_out[s][bt][dc];
        v.x += p.x; v.y += p.y; v.z += p.z; v.w += p.w;
    }
    *(float4*)&out[(size_t)bt * DMODEL + dc] = v;
}

// ---------------------------------------------------------------------------
extern "C" void kernel_launch(void* const* d_in, const int* in_sizes, int n_in,
                              void* d_out, int out_size)
{
    const float* x   = (const float*)d_in[0];
    const float* Wq  = (const float*)d_in[1];
    const float* Wk  = (const float*)d_in[2];
    const float* Wv  = (const float*)d_in[3];
    const float* Wo  = (const float*)d_in[4];
    const float* qns = (const float*)d_in[5];
    const float* kns = (const float*)d_in[6];
    const float* kb  = (const float*)d_in[7];
    const float* vb  = (const float*)d_in[8];
    const int* btab  = (const int*)d_in[9];
    const int* kvl   = (const int*)d_in[10];
    float* out = (float*)d_out;

    const int attn_smem = 2 * 16 * HD * 2 * sizeof(float);   // 64 KB
    cudaFuncSetAttribute(k_attn, cudaFuncAttributeMaxDynamicSharedMemorySize,
                         attn_smem);

    k_rope_table<<<(NTOK * 128 + 255) / 256, 256>>>(kvl);
    k_gemm_qkv<<<dim3(NFQKV / 64, NKSPL), 256>>>(x, Wq, Wk, Wv);
    k_normrope<<<dim3(NTOK, 16), 64>>>(qns, kns);
    k_attn<<<dim3(BATCH * NG, NSPLIT), 256, attn_smem>>>(kb, vb, btab, kvl);
    k_combine<<<BATCH * NG * 8, 64>>>();
    k_gemm_o<<<dim3(DMODEL / 64, NKSPL), 256>>>(Wo);
    k_reduce_out<<<(NTOK * DMODEL / 4 + 255) / 256, 256>>>(out);
}

// round 15
// speedup vs baseline: 1.4506x; 1.4506x over previous
#include <cuda_runtime.h>
#include <math.h>

#define BATCH 16
#define TQ 4
#define DMODEL 2048
#define NH 8
#define NG 4
#define GSZ 2
#define HD 256
#define KVBLK 16
#define WINDOW 1024
#define NBLK 257
#define NTOK 64          // BATCH*TQ
#define NFQKV 4096       // 2048 q + 1024 k + 1024 v
#define NSPLIT 8         // attention KV splits
#define NPART (NSPLIT*2) // partials per query (splits x key-halves)
#define NKSPL 8          // GEMM split-K

typedef unsigned long long u64;

// ---------------- scratch (device globals; no allocation allowed) ----------
__device__ float g_part_qkv[NKSPL][NTOK][NFQKV];        // 8 MB
__device__ float g_obuf[NTOK][DMODEL];                  // attention output (row-major)
__device__ float g_q[NTOK][NH][HD];
__device__ float g_k[NTOK][NG][HD];
__device__ float g_v[NTOK][NG][HD];
__device__ float g_cos[NTOK][HD / 2];
__device__ float g_sin[NTOK][HD / 2];
__device__ float g_pacc[BATCH * NG * 8 * NPART][HD];    // 8 MB
__device__ float g_pm[BATCH * NG * 8 * NPART];
__device__ float g_pl[BATCH * NG * 8 * NPART];
__device__ float g_part_out[NKSPL][NTOK][DMODEL];       // 4 MB

// ---------------- cp.async / mma / f32x2 helpers ----------------------------
__device__ __forceinline__ void cp_async16(void* dst, const void* src)
{
    unsigned d = (unsigned)__cvta_generic_to_shared(dst);
    asm volatile("cp.async.cg.shared.global [%0], [%1], 16;\n" :: "r"(d), "l"(src));
}
__device__ __forceinline__ void cp_commit()
{
    asm volatile("cp.async.commit_group;\n");
}
template <int N>
__device__ __forceinline__ void cp_wait()
{
    asm volatile("cp.async.wait_group %0;\n" :: "n"(N));
}
__device__ __forceinline__ unsigned f2tf32(float f)
{
    unsigned u;
    asm("cvt.rna.tf32.f32 %0, %1;" : "=r"(u) : "f"(f));
    return u;
}
__device__ __forceinline__ void mma_tf32(float* d, const unsigned* a, const unsigned* b)
{
    asm volatile(
        "mma.sync.aligned.m16n8k8.row.col.f32.tf32.tf32.f32 "
        "{%0,%1,%2,%3}, {%4,%5,%6,%7}, {%8,%9}, {%0,%1,%2,%3};\n"
        : "+f"(d[0]), "+f"(d[1]), "+f"(d[2]), "+f"(d[3])
        : "r"(a[0]), "r"(a[1]), "r"(a[2]), "r"(a[3]), "r"(b[0]), "r"(b[1]));
}
__device__ __forceinline__ void fma2(u64& acc, u64 a, u64 b)
{
    asm("fma.rn.f32x2 %0, %1, %2, %0;" : "+l"(acc) : "l"(a), "l"(b));
}
__device__ __forceinline__ u64 mul2(u64 a, u64 b)
{
    u64 r;
    asm("mul.rn.f32x2 %0, %1, %2;" : "=l"(r) : "l"(a), "l"(b));
    return r;
}
__device__ __forceinline__ u64 pack2(float lo, float hi)
{
    u64 r;
    asm("mov.b64 %0, {%1, %2};" : "=l"(r) : "f"(lo), "f"(hi));
    return r;
}
__device__ __forceinline__ float sum2(u64 v)
{
    float lo, hi;
    asm("mov.b64 {%0, %1}, %2;" : "=f"(lo), "=f"(hi) : "l"(v));
    return lo + hi;
}

// ---------------- RoPE table (fp64 accuracy) --------------------------------
__global__ void k_rope_table(const int* __restrict__ kv_lens)
{
    int idx = blockIdx.x * blockDim.x + threadIdx.x;   // 64*128
    if (idx >= NTOK * 128) return;
    int bt = idx >> 7, j = idx & 127;
    int b = bt >> 2, t = bt & 3;
    int pos = kv_lens[b] + t;
    double inv = exp(-((double)j / 128.0) * log(10000.0));
    double ang = (double)pos * inv;
    double sd, cd;
    sincos(ang, &sd, &cd);
    g_cos[bt][j] = (float)cd;
    g_sin[bt][j] = (float)sd;
}

// ---------------- tf32 tensor-core split-K GEMM (R10 config) ----------------
template <int NF>
__device__ __forceinline__ void gemm_tc(
    const float* __restrict__ A,
    const float* __restrict__ W0, int n0,
    const float* __restrict__ W1, int n1,
    const float* __restrict__ W2,
    float* __restrict__ part)
{
    __shared__ float As[2][64][36];   // [m][k], stride 36 -> conflict-free frags
    __shared__ float Ws[2][64][36];   // [n][k]

    const int fbase = blockIdx.x * 64;
    const int split = blockIdx.y;
    const int tid = threadIdx.x;
    const int lane = tid & 31, warp = tid >> 5;
    const int wm = warp >> 2, wn = warp & 3;
    const int kbase = split * 256;
    const int gid = lane >> 2, tig = lane & 3;

    float acc[2][2][4] = {};

    auto issue = [&](int c, int buf) {
        const int kg = kbase + c * 32;
#pragma unroll
        for (int r = 0; r < 2; r++) {
            int o = tid * 2 + r;                 // 0..511
            int row = o >> 3, seg = o & 7;       // 64 rows x 8 chunks
            cp_async16(&As[buf][row][seg * 4],
                       &A[(size_t)row * DMODEL + kg + seg * 4]);
        }
#pragma unroll
        for (int r = 0; r < 2; r++) {
            int o = tid * 2 + r;
            int n = o >> 3, seg = o & 7;
            int f = fbase + n;
            const float* wr;
            if (f < n0)            wr = W0 + (size_t)f * DMODEL;
            else if (f < n0 + n1)  wr = W1 + (size_t)(f - n0) * DMODEL;
            else                   wr = W2 + (size_t)(f - n0 - n1) * DMODEL;
            cp_async16(&Ws[buf][n][seg * 4], wr + kg + seg * 4);
        }
        cp_commit();
    };

    issue(0, 0);
    int buf = 0;
    for (int c = 0; c < 8; c++) {
        if (c < 7) { issue(c + 1, buf ^ 1); cp_wait<1>(); }
        else       cp_wait<0>();
        __syncthreads();
#pragma unroll
        for (int ks = 0; ks < 4; ks++) {
            const int k = ks * 8 + tig;
            unsigned aF[2][4], bF[2][2];
#pragma unroll
            for (int mt = 0; mt < 2; mt++) {
                int m = wm * 32 + mt * 16 + gid;
                aF[mt][0] = f2tf32(As[buf][m][k]);
                aF[mt][1] = f2tf32(As[buf][m + 8][k]);
                aF[mt][2] = f2tf32(As[buf][m][k + 4]);
                aF[mt][3] = f2tf32(As[buf][m + 8][k + 4]);
            }
#pragma unroll
            for (int nt = 0; nt < 2; nt++) {
                int n = wn * 16 + nt * 8 + gid;
                bF[nt][0] = f2tf32(Ws[buf][n][k]);
                bF[nt][1] = f2tf32(Ws[buf][n][k + 4]);
            }
#pragma unroll
            for (int mt = 0; mt < 2; mt++)
#pragma unroll
                for (int nt = 0; nt < 2; nt++)
                    mma_tf32(acc[mt][nt], aF[mt], bF[nt]);
        }
        buf ^= 1;
        __syncthreads();
    }

#pragma unroll
    for (int mt = 0; mt < 2; mt++)
#pragma unroll
        for (int nt = 0; nt < 2; nt++) {
            int m = wm * 32 + mt * 16 + gid;
            int f = fbase + wn * 16 + nt * 8 + tig * 2;
            *(float2*)&part[((size_t)split * NTOK + m) * NF + f] =
                make_float2(acc[mt][nt][0], acc[mt][nt][1]);
            *(float2*)&part[((size_t)split * NTOK + m + 8) * NF + f] =
                make_float2(acc[mt][nt][2], acc[mt][nt][3]);
        }
}

__global__ void __launch_bounds__(256)
k_gemm_qkv(const float* __restrict__ x,
           const float* __restrict__ Wq,
           const float* __restrict__ Wk,
           const float* __restrict__ Wv)
{
    gemm_tc<NFQKV>(x, Wq, 2048, Wk, 1024, Wv, &g_part_qkv[0][0][0]);
}

__global__ void __launch_bounds__(256)
k_gemm_o(const float* __restrict__ Wo)
{
    gemm_tc<DMODEL>(&g_obuf[0][0], Wo, 2048, Wo, 0, Wo, &g_part_out[0][0][0]);
}

// ---------------- split-K reduce + RMSNorm + RoPE (float4, 64 threads) ------
__global__ void k_normrope(const float* __restrict__ q_scale,
                           const float* __restrict__ k_scale)
{
    const int bt = blockIdx.x;
    const int u = blockIdx.y;
    const int t4 = threadIdx.x;        // 0..63
    const int d = t4 * 4;

    int f;
    if (u < 8)       f = u * HD + d;
    else if (u < 12) f = 2048 + (u - 8) * HD + d;
    else             f = 3072 + (u - 12) * HD + d;

    float4 v = {0.f, 0.f, 0.f, 0.f};
#pragma unroll
    for (int s = 0; s < NKSPL; s++) {
        float4 p = *(const float4*)&g_part_qkv[s][bt][f];
        v.x += p.x; v.y += p.y; v.z += p.z; v.w += p.w;
    }

    if (u >= 12) { *(float4*)&g_v[bt][u - 12][d] = v; return; }

    __shared__ __align__(16) float wsum[4];
    __shared__ __align__(16) float sx[256];

    float ss = v.x * v.x + v.y * v.y + v.z * v.z + v.w * v.w;
#pragma unroll
    for (int o = 16; o; o >>= 1) ss += __shfl_xor_sync(0xffffffffu, ss, o);
    if ((t4 & 31) == 0) wsum[t4 >> 5] = ss;
    __syncthreads();
    float rn = rsqrtf((wsum[0] + wsum[1]) / (float)HD + 1e-6f);

    float4 sc = (u < 8) ? *(const float4*)&q_scale[d]
                        : *(const float4*)&k_scale[d];
    float4 sv;
    sv.x = v.x * rn * (1.f + sc.x);
    sv.y = v.y * rn * (1.f + sc.y);
    sv.z = v.z * rn * (1.f + sc.z);
    sv.w = v.w * rn * (1.f + sc.w);
    *(float4*)&sx[d] = sv;
    __syncthreads();

    const int j = d & 127;
    float4 c = *(const float4*)&g_cos[bt][j];
    float4 s = *(const float4*)&g_sin[bt][j];
    float4 x1 = *(const float4*)&sx[j];
    float4 x2 = *(const float4*)&sx[j + 128];
    float4 o;
    if (d < 128) {
        o.x = x1.x * c.x - x2.x * s.x; o.y = x1.y * c.y - x2.y * s.y;
        o.z = x1.z * c.z - x2.z * s.z; o.w = x1.w * c.w - x2.w * s.w;
    } else {
        o.x = x2.x * c.x + x1.x * s.x; o.y = x2.y * c.y + x1.y * s.y;
        o.z = x2.z * c.z + x1.z * s.z; o.w = x2.w * c.w + x1.w * s.w;
    }
    if (u < 8) *(float4*)&g_q[bt][u][d] = o;
    else       *(float4*)&g_k[bt][u - 8][d] = o;
}

// ---------------- attention tile loader: K or V separately (R10) ------------
template <int WHICH>   // 0 = K, 1 = V
__device__ __forceinline__ void attn_issue_one(
    float* __restrict__ sDst,
    int k0, int kvl, int hi, int b, int g,
    const float* __restrict__ kb, const float* __restrict__ vb,
    const int* __restrict__ btab, int tid)
{
    const int key = tid >> 4;
    const int j = tid & 15;
    const int kpos = k0 + key;
    const float* p;
    if (kpos < kvl) {
        int blk = btab[b * NBLK + (kpos >> 4)];
        size_t off = (((size_t)blk * NG + g) * KVBLK + (kpos & 15)) * HD;
        p = (WHICH ? vb : kb) + off;
    } else if (kpos <= hi) {
        int tf = kpos - kvl;
        p = WHICH ? &g_v[b * TQ + tf][g][0] : &g_k[b * TQ + tf][g][0];
    } else {
        p = WHICH ? &g_v[0][0][0] : &g_k[0][0][0];
    }
    float* d = sDst + key * HD;
#pragma unroll
    for (int c = 0; c < 4; c++) {
        int f = (j + 16 * c) * 4;
        cp_async16(d + f, p + f);
    }
    cp_commit();
}

// ---------------- flash-decode attention: 2q x 8k, split K/V waits (R10) ----
__global__ void __launch_bounds__(256, 3)
k_attn(const float* __restrict__ k_blocks,
       const float* __restrict__ v_blocks,
       const int* __restrict__ block_tables,
       const int* __restrict__ kv_lens)
{
    extern __shared__ float sm[];
    float* sK0 = sm;
    float* sV0 = sm + 2 * 16 * HD;

    const int bg = blockIdx.x;
    const int b = bg >> 2, g = bg & 3;
    const int sp = blockIdx.y;
    const int tid = threadIdx.x;
    const int warp = tid >> 5, lane = tid & 31;
    const int qp = warp >> 1;
    const int kh = warp & 1;

    const int kvl = kv_lens[b];
    const int lo = max(0, kvl - (WINDOW - 1));
    const int hi = kvl + 3;
    const int L = hi - lo + 1;
    const int chunk = (L + NSPLIT - 1) / NSPLIT;
    const int kstart = lo + sp * chunk;
    const int kend = min(kstart + chunk, hi + 1);

    // queries packed as 4 x f32x2 per half (8 dims per lane)
    u64 qv[2][4];
    int post[2];
#pragma unroll
    for (int j = 0; j < 2; j++) {
        int qi = qp * 2 + j;
        int gi = qi >> 2, t = qi & 3;
        ulonglong2 a = *(const ulonglong2*)&g_q[b * TQ + t][g * GSZ + gi][lane * 4];
        ulonglong2 c = *(const ulonglong2*)&g_q[b * TQ + t][g * GSZ + gi][128 + lane * 4];
        qv[j][0] = a.x; qv[j][1] = a.y; qv[j][2] = c.x; qv[j][3] = c.y;
        post[j] = kvl + t;
    }

    float m[2] = {-INFINITY, -INFINITY};
    float l[2] = {0.f, 0.f};
    u64 av[2][4] = {};          // packed accumulators (8 dims per lane)

    if (kstart < kend) {
        attn_issue_one<0>(sK0, kstart, kvl, hi, b, g,
                          k_blocks, v_blocks, block_tables, tid);
        attn_issue_one<1>(sV0, kstart, kvl, hi, b, g,
                          k_blocks, v_blocks, block_tables, tid);
    }

    int buf = 0;
    for (int k0 = kstart; k0 < kend; k0 += 16) {
        const int nk = min(16, kend - k0);
        const bool more = (k0 + 16 < kend);
        if (more) {
            attn_issue_one<0>(sK0 + (buf ^ 1) * 16 * HD, k0 + 16, kvl, hi, b, g,
                              k_blocks, v_blocks, block_tables, tid);
            attn_issue_one<1>(sV0 + (buf ^ 1) * 16 * HD, k0 + 16, kvl, hi, b, g,
                              k_blocks, v_blocks, block_tables, tid);
            cp_wait<3>();       // K_i done; V_i, K_{i+1}, V_{i+1} in flight
        } else {
            cp_wait<1>();       // K_i done; V_i in flight
        }
        __syncthreads();

        const float* K = sK0 + buf * 16 * HD;
        const float* V = sV0 + buf * 16 * HD;

        // ---- scores: packed f32x2 dot products (V still in flight) ----
        float s[2][8];
#pragma unroll
        for (int kk = 0; kk < 8; kk++) {
            const float* kr = K + (kh * 8 + kk) * HD;
            ulonglong2 kA = *(const ulonglong2*)(kr + lane * 4);
            ulonglong2 kB = *(const ulonglong2*)(kr + 128 + lane * 4);
#pragma unroll
            for (int j = 0; j < 2; j++) {
                u64 d2 = 0;                 // bits of (0.f, 0.f)
                fma2(d2, qv[j][0], kA.x);
                fma2(d2, qv[j][1], kA.y);
                fma2(d2, qv[j][2], kB.x);
                fma2(d2, qv[j][3], kB.y);
                s[j][kk] = sum2(d2);
            }
        }
#pragma unroll
        for (int j = 0; j < 2; j++)
#pragma unroll
            for (int kk = 0; kk < 8; kk++) {
                float d = s[j][kk];
#pragma unroll
                for (int o = 16; o; o >>= 1) d += __shfl_xor_sync(0xffffffffu, d, o);
                int kpos = k0 + kh * 8 + kk;
                bool ok = (kh * 8 + kk) < nk && kpos <= post[j]
                          && kpos > post[j] - WINDOW;
                s[j][kk] = ok ? d * 0.0625f : -INFINITY;
            }

        // ---- online softmax update ----
#pragma unroll
        for (int j = 0; j < 2; j++) {
            float tm = s[j][0];
#pragma unroll
            for (int kk = 1; kk < 8; kk++) tm = fmaxf(tm, s[j][kk]);
            if (tm == -INFINITY) {
#pragma unroll
                for (int kk = 0; kk < 8; kk++) s[j][kk] = 0.f;
                continue;
            }
            float mn = fmaxf(m[j], tm);
            float co = __expf(m[j] - mn);
            float ls = 0.f;
#pragma unroll
            for (int kk = 0; kk < 8; kk++) {
                s[j][kk] = __expf(s[j][kk] - mn);
                ls += s[j][kk];
            }
            l[j] = l[j] * co + ls;
            u64 cop = pack2(co, co);
#pragma unroll
            for (int i = 0; i < 4; i++) av[j][i] = mul2(av[j][i], cop);
            m[j] = mn;
        }

        if (more) cp_wait<2>();   // V_i done; next tile still in flight
        else      cp_wait<0>();
        __syncthreads();

        // ---- PV: packed f32x2 accumulate ----
#pragma unroll
        for (int kk = 0; kk < 8; kk++) {
            const float* vr = V + (kh * 8 + kk) * HD;
            ulonglong2 vA = *(const ulonglong2*)(vr + lane * 4);
            ulonglong2 vB = *(const ulonglong2*)(vr + 128 + lane * 4);
#pragma unroll
            for (int j = 0; j < 2; j++) {
                u64 pp = pack2(s[j][kk], s[j][kk]);
                fma2(av[j][0], pp, vA.x);
                fma2(av[j][1], pp, vA.y);
                fma2(av[j][2], pp, vB.x);
                fma2(av[j][3], pp, vB.y);
            }
        }
        buf ^= 1;
        __syncthreads();
    }

#pragma unroll
    for (int j = 0; j < 2; j++) {
        int qidx = bg * 8 + qp * 2 + j;
        int pi = (qidx * NSPLIT + sp) * 2 + kh;
        if (lane == 0) { g_pm[pi] = m[j]; g_pl[pi] = l[j]; }
        ulonglong2 oA = {av[j][0], av[j][1]};
        ulonglong2 oB = {av[j][2], av[j][3]};
        *(ulonglong2*)&g_pacc[pi][lane * 4] = oA;
        *(ulonglong2*)&g_pacc[pi][128 + lane * 4] = oB;
    }
}

// ---------------- combine partial softmax (float4, 64 threads) --------------
__global__ void k_combine()
{
    const int qidx = blockIdx.x;   // 512
    const int d = threadIdx.x * 4; // 0..252

    float M = -INFINITY;
#pragma unroll
    for (int s = 0; s < NPART; s++) M = fmaxf(M, g_pm[qidx * NPART + s]);
    float Lt = 0.f;
    float4 od = {0.f, 0.f, 0.f, 0.f};
#pragma unroll
    for (int s = 0; s < NPART; s++) {
        float ms = g_pm[qidx * NPART + s];
        float w = (ms == -INFINITY) ? 0.f : __expf(ms - M);
        Lt += g_pl[qidx * NPART + s] * w;
        float4 p = *(const float4*)&g_pacc[qidx * NPART + s][d];
        od.x += p.x * w; od.y += p.y * w; od.z += p.z * w; od.w += p.w * w;
    }
    float inv = 1.f / Lt;

    int t = qidx & 3;
    int gi = (qidx >> 2) & 1;
    int g = (qidx >> 3) & 3;
    int b = qidx >> 5;
    float4 o = {od.x * inv, od.y * inv, od.z * inv, od.w * inv};
    *(float4*)&g_obuf[b * TQ + t][(g * GSZ + gi) * HD + d] = o;
}

// ---------------- final split-K reduce to output ---------------------------
__global__ void k_reduce_out(float* __restrict__ out)
{
    int idx = blockIdx.x * blockDim.x + threadIdx.x;   // 64*2048/4
    if (idx >= NTOK * DMODEL / 4) return;
    int bt = idx / (DMODEL / 4), dc = (idx % (DMODEL / 4)) * 4;
    float4 v = {0.f, 0.f, 0.f, 0.f};
#pragma unroll
    for (int s = 0; s < NKSPL; s++) {
        float4 p = *(const float4*)&g_part_out[s][bt][dc];
        v.x += p.x; v.y += p.y; v.z += p.z; v.w += p.w;
    }
    *(float4*)&out[(size_t)bt * DMODEL + dc] = v;
}

// ---------------------------------------------------------------------------
extern "C" void kernel_launch(void* const* d_in, const int* in_sizes, int n_in,
                              void* d_out, int out_size)
{
    const float* x   = (const float*)d_in[0];
    const float* Wq  = (const float*)d_in[1];
    const float* Wk  = (const float*)d_in[2];
    const float* Wv  = (const float*)d_in[3];
    const float* Wo  = (const float*)d_in[4];
    const float* qns = (const float*)d_in[5];
    const float* kns = (const float*)d_in[6];
    const float* kb  = (const float*)d_in[7];
    const float* vb  = (const float*)d_in[8];
    const int* btab  = (const int*)d_in[9];
    const int* kvl   = (const int*)d_in[10];
    float* out = (float*)d_out;

    const int attn_smem = 2 * 16 * HD * 2 * sizeof(float);   // 64 KB
    cudaFuncSetAttribute(k_attn, cudaFuncAttributeMaxDynamicSharedMemorySize,
                         attn_smem);

    k_rope_table<<<(NTOK * 128 + 255) / 256, 256>>>(kvl);
    k_gemm_qkv<<<dim3(NFQKV / 64, NKSPL), 256>>>(x, Wq, Wk, Wv);
    k_normrope<<<dim3(NTOK, 16), 64>>>(qns, kns);
    k_attn<<<dim3(BATCH * NG, NSPLIT), 256, attn_smem>>>(kb, vb, btab, kvl);
    k_combine<<<BATCH * NG * 8, 64>>>();
    k_gemm_o<<<dim3(DMODEL / 64, NKSPL), 256>>>(Wo);
    k_reduce_out<<<(NTOK * DMODEL / 4 + 255) / 256, 256>>>(out);
}